// round 1
// baseline (speedup 1.0000x reference)
#include <cuda_runtime.h>
#include <cuda_bf16.h>
#include <cstdint>

#define BB 64
#define TT 512
#define SS 4
#define HH 512
#define VV 10000

// ---------------- device scratch (no cudaMalloc allowed) ----------------
__device__ float g_lse[SS * HH];                        // logsumexp over V per (s,h)
__device__ float g_leT[(size_t)SS * VV * HH];           // [s][v][h] = log_emis transposed
__device__ float g_E[(size_t)BB * TT * HH];             // exp(em - smax) (priors folded at t=0)
__device__ float g_smax[BB * TT];                       // per (b,t) max used in E
__device__ __nv_bfloat16 g_P[HH * HH];                  // softmax(tran) row-major [j][k], bf16
__device__ int g_is64;                                  // 1 if obs/lengths are int64

// ---------------- helpers ----------------
__device__ __forceinline__ float bflo(unsigned u) { return __uint_as_float(u << 16); }
__device__ __forceinline__ float bfhi(unsigned u) { return __uint_as_float(u & 0xffff0000u); }

__device__ __forceinline__ float warp_sum(float v) {
    #pragma unroll
    for (int o = 16; o; o >>= 1) v += __shfl_xor_sync(0xffffffffu, v, o);
    return v;
}
__device__ __forceinline__ float warp_max(float v) {
    #pragma unroll
    for (int o = 16; o; o >>= 1) v = fmaxf(v, __shfl_xor_sync(0xffffffffu, v, o));
    return v;
}

// ---------------- kernel 0: detect int64 vs int32 indices ----------------
__global__ void detect_kernel(const int* obs32) {
    if (threadIdx.x == 0) {
        int f = 1;
        for (int i = 0; i < 128; ++i)
            if (obs32[2 * i + 1] != 0) { f = 0; break; }
        g_is64 = f;
    }
}

// ---------------- kernel 1: lse[s,h] = logsumexp_v emis[s,h,v] ----------------
__global__ void lse_kernel(const float* __restrict__ emis) {
    int row = blockIdx.x;                  // 0 .. S*H-1
    const float4* x4 = (const float4*)(emis + (size_t)row * VV);  // 2500 float4
    int tid = threadIdx.x;
    __shared__ float sr[256];

    float m = -1e30f;
    for (int i = tid; i < VV / 4; i += 256) {
        float4 v = x4[i];
        m = fmaxf(m, fmaxf(fmaxf(v.x, v.y), fmaxf(v.z, v.w)));
    }
    sr[tid] = m; __syncthreads();
    for (int s = 128; s; s >>= 1) { if (tid < s) sr[tid] = fmaxf(sr[tid], sr[tid + s]); __syncthreads(); }
    m = sr[0]; __syncthreads();

    float sum = 0.f;
    for (int i = tid; i < VV / 4; i += 256) {
        float4 v = x4[i];
        sum += expf(v.x - m) + expf(v.y - m) + expf(v.z - m) + expf(v.w - m);
    }
    sr[tid] = sum; __syncthreads();
    for (int s = 128; s; s >>= 1) { if (tid < s) sr[tid] += sr[tid + s]; __syncthreads(); }
    if (tid == 0) g_lse[row] = m + logf(sr[0]);
}

// ---------------- kernel 2: leT[s][v][h] = emis[s][h][v] - lse[s][h] ----------------
__global__ void transpose_kernel(const float* __restrict__ emis) {
    __shared__ float tile[32][33];
    int s  = blockIdx.z;
    int v0 = blockIdx.x * 32;
    int h0 = blockIdx.y * 32;
    int tx = threadIdx.x, ty = threadIdx.y;

    #pragma unroll
    for (int r = 0; r < 4; ++r) {
        int h = h0 + ty + 8 * r;
        int v = v0 + tx;
        float val = 0.f;
        if (v < VV) val = emis[((size_t)s * HH + h) * VV + v] - g_lse[s * HH + h];
        tile[ty + 8 * r][tx] = val;
    }
    __syncthreads();
    #pragma unroll
    for (int r = 0; r < 4; ++r) {
        int v = v0 + ty + 8 * r;
        int h = h0 + tx;
        if (v < VV) g_leT[((size_t)s * VV + v) * HH + h] = tile[tx][ty + 8 * r];
    }
}

// ---------------- kernel 3: P = softmax(tran rows) as bf16 ----------------
__global__ void psoftmax_kernel(const float* __restrict__ tran) {
    int j = blockIdx.x;
    const float* row = tran + (size_t)j * HH;
    int tid = threadIdx.x;                  // 256 threads, 2 elems each
    __shared__ float sr[256];

    float a = row[tid], b = row[tid + 256];
    sr[tid] = fmaxf(a, b); __syncthreads();
    for (int s = 128; s; s >>= 1) { if (tid < s) sr[tid] = fmaxf(sr[tid], sr[tid + s]); __syncthreads(); }
    float m = sr[0]; __syncthreads();

    float ea = expf(a - m), eb = expf(b - m);
    sr[tid] = ea + eb; __syncthreads();
    for (int s = 128; s; s >>= 1) { if (tid < s) sr[tid] += sr[tid + s]; __syncthreads(); }
    float inv = 1.0f / sr[0];
    g_P[(size_t)j * HH + tid]       = __float2bfloat16(ea * inv);
    g_P[(size_t)j * HH + tid + 256] = __float2bfloat16(eb * inv);
}

// ---------------- kernel 4: gather em, compute smax & E = exp(em - smax) ----------------
__global__ void emE_kernel(const void* __restrict__ obs_raw,
                           const float* __restrict__ priors) {
    int t = blockIdx.x, b = blockIdx.y;
    int tid = threadIdx.x;                 // 128 threads, 4 h's each via float4
    int lane = tid & 31, wid = tid >> 5;
    __shared__ float sm[4];

    int o[SS];
    if (g_is64) {
        const long long* p = (const long long*)obs_raw + ((size_t)(b * TT + t)) * SS;
        #pragma unroll
        for (int s = 0; s < SS; ++s) o[s] = (int)p[s];
    } else {
        const int* p = (const int*)obs_raw + ((size_t)(b * TT + t)) * SS;
        #pragma unroll
        for (int s = 0; s < SS; ++s) o[s] = p[s];
    }

    float4 acc = make_float4(0.f, 0.f, 0.f, 0.f);
    #pragma unroll
    for (int s = 0; s < SS; ++s) {
        const float4* r = (const float4*)(g_leT + ((size_t)s * VV + o[s]) * HH);
        float4 v = r[tid];
        acc.x += v.x; acc.y += v.y; acc.z += v.z; acc.w += v.w;
    }
    acc.x *= 0.25f; acc.y *= 0.25f; acc.z *= 0.25f; acc.w *= 0.25f;

    if (t == 0) {
        float4 pr = ((const float4*)priors)[tid];
        acc.x += pr.x; acc.y += pr.y; acc.z += pr.z; acc.w += pr.w;
    }

    float m = fmaxf(fmaxf(acc.x, acc.y), fmaxf(acc.z, acc.w));
    m = warp_max(m);
    if (lane == 0) sm[wid] = m;
    __syncthreads();
    m = fmaxf(fmaxf(sm[0], sm[1]), fmaxf(sm[2], sm[3]));

    float4 e;
    e.x = __expf(acc.x - m); e.y = __expf(acc.y - m);
    e.z = __expf(acc.z - m); e.w = __expf(acc.w - m);
    ((float4*)(g_E + ((size_t)(b * TT + t)) * HH))[tid] = e;
    if (tid == 0) g_smax[b * TT + t] = m;
}

// ---------------- kernel 5: forward recursion, one CTA per batch ----------------
__global__ void __launch_bounds__(512, 1)
forward_kernel(const void* __restrict__ lengths_raw, float* __restrict__ out) {
    int b = blockIdx.x;
    int tid = threadIdx.x;
    int lane = tid & 31, wid = tid >> 5;

    __shared__ float p_s[HH];
    __shared__ float part[8][528];   // padded
    __shared__ float red[16];
    __shared__ float bcast[2];       // [0]=1/S, [1]=log(S)

    int len = g_is64 ? (int)((const long long*)lengths_raw)[b]
                     : ((const int*)lengths_raw)[b];

    const float* Eb  = g_E + (size_t)b * TT * HH;
    const float* smx = g_smax + (size_t)b * TT;

    // ---- t = 0 ----
    float w = Eb[tid];
    float s = warp_sum(w);
    if (lane == 0) red[wid] = s;
    __syncthreads();
    if (tid == 0) {
        float S = 0.f;
        #pragma unroll
        for (int r = 0; r < 16; ++r) S += red[r];
        bcast[0] = 1.0f / S;
        bcast[1] = logf(S);
    }
    __syncthreads();
    float c = smx[0] + bcast[1];
    p_s[tid] = w * bcast[0];
    __syncthreads();

    // ---- t = 1 .. len-1 ----
    int g = tid >> 6, i = tid & 63;          // 8 j-groups of 64 threads; thread owns k = 8i..8i+7
    const uint4* Pg = (const uint4*)g_P + (size_t)(g * 64) * 64 + i;
    const float* pp = p_s + g * 64;

    for (int t = 1; t < len; ++t) {
        float a0 = 0.f, a1 = 0.f, a2 = 0.f, a3 = 0.f, a4 = 0.f, a5 = 0.f, a6 = 0.f, a7 = 0.f;
        #pragma unroll 4
        for (int jj = 0; jj < 64; jj += 4) {
            float4 pj = *(const float4*)(pp + jj);
            uint4 q0 = Pg[(jj + 0) * 64];
            uint4 q1 = Pg[(jj + 1) * 64];
            uint4 q2 = Pg[(jj + 2) * 64];
            uint4 q3 = Pg[(jj + 3) * 64];
            a0 += pj.x * bflo(q0.x); a1 += pj.x * bfhi(q0.x);
            a2 += pj.x * bflo(q0.y); a3 += pj.x * bfhi(q0.y);
            a4 += pj.x * bflo(q0.z); a5 += pj.x * bfhi(q0.z);
            a6 += pj.x * bflo(q0.w); a7 += pj.x * bfhi(q0.w);
            a0 += pj.y * bflo(q1.x); a1 += pj.y * bfhi(q1.x);
            a2 += pj.y * bflo(q1.y); a3 += pj.y * bfhi(q1.y);
            a4 += pj.y * bflo(q1.z); a5 += pj.y * bfhi(q1.z);
            a6 += pj.y * bflo(q1.w); a7 += pj.y * bfhi(q1.w);
            a0 += pj.z * bflo(q2.x); a1 += pj.z * bfhi(q2.x);
            a2 += pj.z * bflo(q2.y); a3 += pj.z * bfhi(q2.y);
            a4 += pj.z * bflo(q2.z); a5 += pj.z * bfhi(q2.z);
            a6 += pj.z * bflo(q2.w); a7 += pj.z * bfhi(q2.w);
            a0 += pj.w * bflo(q3.x); a1 += pj.w * bfhi(q3.x);
            a2 += pj.w * bflo(q3.y); a3 += pj.w * bfhi(q3.y);
            a4 += pj.w * bflo(q3.z); a5 += pj.w * bfhi(q3.z);
            a6 += pj.w * bflo(q3.w); a7 += pj.w * bfhi(q3.w);
        }
        // stash partials
        float4* dst = (float4*)&part[g][i * 8];
        dst[0] = make_float4(a0, a1, a2, a3);
        dst[1] = make_float4(a4, a5, a6, a7);
        __syncthreads();

        // thread k = tid: reduce 8 partials, apply E, global reduce
        int k = tid;
        float v = part[0][k] + part[1][k] + part[2][k] + part[3][k]
                + part[4][k] + part[5][k] + part[6][k] + part[7][k];
        float wk = Eb[(size_t)t * HH + k] * v;

        float ss = warp_sum(wk);
        if (lane == 0) red[wid] = ss;
        __syncthreads();
        if (tid == 0) {
            float S = 0.f;
            #pragma unroll
            for (int r = 0; r < 16; ++r) S += red[r];
            bcast[0] = 1.0f / S;
            bcast[1] = logf(S);
        }
        __syncthreads();
        c += smx[t] + bcast[1];
        p_s[k] = wk * bcast[0];
        __syncthreads();
    }

    if (tid == 0) out[b] = c;
}

// ---------------- launcher ----------------
extern "C" void kernel_launch(void* const* d_in, const int* in_sizes, int n_in,
                              void* d_out, int out_size) {
    const void*  obs     = d_in[0];
    const void*  lengths = d_in[1];
    const float* emis    = (const float*)d_in[2];
    const float* tran    = (const float*)d_in[3];
    const float* priors  = (const float*)d_in[4];
    float* out = (float*)d_out;

    detect_kernel<<<1, 32>>>((const int*)obs);
    lse_kernel<<<SS * HH, 256>>>(emis);
    transpose_kernel<<<dim3((VV + 31) / 32, HH / 32, SS), dim3(32, 8)>>>(emis);
    psoftmax_kernel<<<HH, 256>>>(tran);
    emE_kernel<<<dim3(TT, BB), 128>>>(obs, priors);
    forward_kernel<<<BB, 512>>>(lengths, out);
}

// round 3
// speedup vs baseline: 2.1311x; 2.1311x over previous
#include <cuda_runtime.h>
#include <cuda_bf16.h>
#include <cuda_fp16.h>
#include <cuda_fp8.h>
#include <cstdint>

#define BB 64
#define TT 512
#define SS 4
#define HH 512
#define VV 10000
#define HALFH 256

// ---------------- device scratch ----------------
__device__ float g_lse[SS * HH];
__device__ float g_leT[(size_t)SS * VV * HH];          // [s][v][h]
__device__ float g_E[(size_t)BB * TT * HH];            // exp(em - smax)
__device__ float g_smax[BB * TT];
__device__ unsigned char g_P8[HH * HH];                // e4m3(P * 256), row-major [j][k]
__device__ float g_corr[HH];                           // per-row fp8 row-sum correction
__device__ int g_is64;

// ---------------- helpers ----------------
__device__ __forceinline__ float warp_sum(float v) {
    #pragma unroll
    for (int o = 16; o; o >>= 1) v += __shfl_xor_sync(0xffffffffu, v, o);
    return v;
}
__device__ __forceinline__ float warp_max(float v) {
    #pragma unroll
    for (int o = 16; o; o >>= 1) v = fmaxf(v, __shfl_xor_sync(0xffffffffu, v, o));
    return v;
}
__device__ __forceinline__ uint32_t smem_u32(const void* p) {
    uint32_t a;
    asm("{ .reg .u64 t; cvta.to.shared.u64 t, %1; cvt.u32.u64 %0, t; }" : "=r"(a) : "l"(p));
    return a;
}
__device__ __forceinline__ unsigned cvt_e4m3x2(unsigned short s) {
    unsigned r;
    asm("cvt.rn.f16x2.e4m3x2 %0, %1;" : "=r"(r) : "h"(s));
    return r;
}
__device__ __forceinline__ __half2 u32_h2(unsigned u) {
    __half2 h;
    *reinterpret_cast<unsigned*>(&h) = u;
    return h;
}
__device__ __forceinline__ void mbar_init(uint32_t m, unsigned cnt) {
    asm volatile("mbarrier.init.shared.b64 [%0], %1;" :: "r"(m), "r"(cnt) : "memory");
}
// RELEASE at CLUSTER scope: orders prior st.shared::cluster stores before the
// peer's acquire-wait observes the phase flip. (R2 bug: default .cta scope.)
__device__ __forceinline__ void mbar_arrive_remote(uint32_t m_local, unsigned peer) {
    asm volatile("{\n\t.reg .b32 r;\n\t"
                 "mapa.shared::cluster.u32 r, %0, %1;\n\t"
                 "mbarrier.arrive.release.cluster.shared::cluster.b64 _, [r];\n\t}"
                 :: "r"(m_local), "r"(peer) : "memory");
}
__device__ __forceinline__ void st_remote_f32(uint32_t a_local, unsigned peer, float v) {
    asm volatile("{\n\t.reg .b32 r;\n\t"
                 "mapa.shared::cluster.u32 r, %0, %1;\n\t"
                 "st.shared::cluster.f32 [r], %2;\n\t}"
                 :: "r"(a_local), "r"(peer), "f"(v) : "memory");
}
__device__ __forceinline__ void mbar_wait(uint32_t m, unsigned parity) {
    asm volatile("{\n\t.reg .pred P;\n\t"
                 "WL_%=:\n\t"
                 "mbarrier.try_wait.parity.acquire.cluster.shared::cta.b64 P, [%0], %1, 0x989680;\n\t"
                 "@P bra WD_%=;\n\t"
                 "bra WL_%=;\n\t"
                 "WD_%=:\n\t}"
                 :: "r"(m), "r"(parity) : "memory");
}
#define CLUSTER_SYNC_() do { \
    asm volatile("barrier.cluster.arrive.aligned;" ::: "memory"); \
    asm volatile("barrier.cluster.wait.aligned;" ::: "memory"); } while (0)

// ---------------- kernel 0: detect int64 vs int32 ----------------
__global__ void detect_kernel(const int* obs32) {
    if (threadIdx.x == 0) {
        int f = 1;
        for (int i = 0; i < 128; ++i)
            if (obs32[2 * i + 1] != 0) { f = 0; break; }
        g_is64 = f;
    }
}

// ---------------- kernel 1: lse over V ----------------
__global__ void lse_kernel(const float* __restrict__ emis) {
    int row = blockIdx.x;
    const float4* x4 = (const float4*)(emis + (size_t)row * VV);
    int tid = threadIdx.x;
    __shared__ float sr[256];

    float m = -1e30f;
    for (int i = tid; i < VV / 4; i += 256) {
        float4 v = x4[i];
        m = fmaxf(m, fmaxf(fmaxf(v.x, v.y), fmaxf(v.z, v.w)));
    }
    sr[tid] = m; __syncthreads();
    for (int s = 128; s; s >>= 1) { if (tid < s) sr[tid] = fmaxf(sr[tid], sr[tid + s]); __syncthreads(); }
    m = sr[0]; __syncthreads();

    float sum = 0.f;
    for (int i = tid; i < VV / 4; i += 256) {
        float4 v = x4[i];
        sum += expf(v.x - m) + expf(v.y - m) + expf(v.z - m) + expf(v.w - m);
    }
    sr[tid] = sum; __syncthreads();
    for (int s = 128; s; s >>= 1) { if (tid < s) sr[tid] += sr[tid + s]; __syncthreads(); }
    if (tid == 0) g_lse[row] = m + logf(sr[0]);
}

// ---------------- kernel 2: transpose with lse subtract ----------------
__global__ void transpose_kernel(const float* __restrict__ emis) {
    __shared__ float tile[32][33];
    int s  = blockIdx.z;
    int v0 = blockIdx.x * 32;
    int h0 = blockIdx.y * 32;
    int tx = threadIdx.x, ty = threadIdx.y;

    #pragma unroll
    for (int r = 0; r < 4; ++r) {
        int h = h0 + ty + 8 * r;
        int v = v0 + tx;
        float val = 0.f;
        if (v < VV) val = emis[((size_t)s * HH + h) * VV + v] - g_lse[s * HH + h];
        tile[ty + 8 * r][tx] = val;
    }
    __syncthreads();
    #pragma unroll
    for (int r = 0; r < 4; ++r) {
        int v = v0 + ty + 8 * r;
        int h = h0 + tx;
        if (v < VV) g_leT[((size_t)s * VV + v) * HH + h] = tile[tx][ty + 8 * r];
    }
}

// ---------------- kernel 3: P8 = e4m3(softmax(tran)*256) + row-sum corr ----------------
__global__ void psoftmax_kernel(const float* __restrict__ tran) {
    int j = blockIdx.x;
    const float* row = tran + (size_t)j * HH;
    int tid = threadIdx.x;
    __shared__ float sr[256];

    float a = row[tid], b = row[tid + 256];
    sr[tid] = fmaxf(a, b); __syncthreads();
    for (int s = 128; s; s >>= 1) { if (tid < s) sr[tid] = fmaxf(sr[tid], sr[tid + s]); __syncthreads(); }
    float m = sr[0]; __syncthreads();

    float ea = expf(a - m), eb = expf(b - m);
    sr[tid] = ea + eb; __syncthreads();
    for (int s = 128; s; s >>= 1) { if (tid < s) sr[tid] += sr[tid + s]; __syncthreads(); }
    float inv = 256.0f / sr[0];
    __syncthreads();

    __nv_fp8_storage_t qa = __nv_cvt_float_to_fp8(ea * inv, __NV_SATFINITE, __NV_E4M3);
    __nv_fp8_storage_t qb = __nv_cvt_float_to_fp8(eb * inv, __NV_SATFINITE, __NV_E4M3);
    g_P8[(size_t)j * HH + tid]       = qa;
    g_P8[(size_t)j * HH + tid + 256] = qb;

    // exact dequant sum of the quantized row -> correction factor
    __half_raw ha = __nv_cvt_fp8_to_halfraw(qa, __NV_E4M3);
    __half_raw hb = __nv_cvt_fp8_to_halfraw(qb, __NV_E4M3);
    float da = __half2float(*(__half*)&ha) + __half2float(*(__half*)&hb);
    sr[tid] = da; __syncthreads();
    for (int s = 128; s; s >>= 1) { if (tid < s) sr[tid] += sr[tid + s]; __syncthreads(); }
    if (tid == 0) g_corr[j] = 256.0f / sr[0];
}

// ---------------- kernel 4: gather em, smax & E ----------------
__global__ void emE_kernel(const void* __restrict__ obs_raw,
                           const float* __restrict__ priors) {
    int t = blockIdx.x, b = blockIdx.y;
    int tid = threadIdx.x;
    int lane = tid & 31, wid = tid >> 5;
    __shared__ float sm[4];

    int o[SS];
    if (g_is64) {
        const long long* p = (const long long*)obs_raw + ((size_t)(b * TT + t)) * SS;
        #pragma unroll
        for (int s = 0; s < SS; ++s) o[s] = (int)p[s];
    } else {
        const int* p = (const int*)obs_raw + ((size_t)(b * TT + t)) * SS;
        #pragma unroll
        for (int s = 0; s < SS; ++s) o[s] = p[s];
    }

    float4 acc = make_float4(0.f, 0.f, 0.f, 0.f);
    #pragma unroll
    for (int s = 0; s < SS; ++s) {
        const float4* r = (const float4*)(g_leT + ((size_t)s * VV + o[s]) * HH);
        float4 v = r[tid];
        acc.x += v.x; acc.y += v.y; acc.z += v.z; acc.w += v.w;
    }
    acc.x *= 0.25f; acc.y *= 0.25f; acc.z *= 0.25f; acc.w *= 0.25f;

    if (t == 0) {
        float4 pr = ((const float4*)priors)[tid];
        acc.x += pr.x; acc.y += pr.y; acc.z += pr.z; acc.w += pr.w;
    }

    float m = fmaxf(fmaxf(acc.x, acc.y), fmaxf(acc.z, acc.w));
    m = warp_max(m);
    if (lane == 0) sm[wid] = m;
    __syncthreads();
    m = fmaxf(fmaxf(sm[0], sm[1]), fmaxf(sm[2], sm[3]));

    float4 e;
    e.x = __expf(acc.x - m); e.y = __expf(acc.y - m);
    e.z = __expf(acc.z - m); e.w = __expf(acc.w - m);
    ((float4*)(g_E + ((size_t)(b * TT + t)) * HH))[tid] = e;
    if (tid == 0) g_smax[b * TT + t] = m;
}

// ---------------- kernel 5: forward recursion, 2-CTA cluster per batch ----------------
// smem layout (bytes)
#define SM_P     0            // 256 x 512 fp8 = 131072
#define SM_PART  131072       // 8 x 512 floats = 16384
#define SM_PH    147456       // 256 x u32 (half2 bcast p) = 1024
#define SM_RECV  148480       // 256 floats = 1024
#define SM_RED   149504       // 16 floats
#define SM_BCAST 149568       // float (local S_r)
#define SM_SRECV 149572       // float (peer S_r)
#define SM_MBARP 149576       // 8B
#define SM_MBARS 149584       // 8B
#define SMEM_TOTAL 149632

#define LOG256 5.545177444479562f

__global__ void __launch_bounds__(512, 1) __cluster_dims__(2, 1, 1)
forward_kernel(const void* __restrict__ lengths_raw, float* __restrict__ out) {
    extern __shared__ char sm[];
    const int tid  = threadIdx.x;
    const int b    = blockIdx.x >> 1;
    const unsigned rank = blockIdx.x & 1;
    const unsigned peer = rank ^ 1;
    const int lane = tid & 31, wid = tid >> 5;
    const bool own = ((unsigned)(tid >> 8) == rank);   // global k = tid belongs to my half
    const int u = tid & 255;

    const uint32_t sbase = smem_u32(sm);
    const uint32_t mbarP = sbase + SM_MBARP;
    const uint32_t mbarS = sbase + SM_MBARS;
    float*    part  = (float*)(sm + SM_PART);
    unsigned* p_h   = (unsigned*)(sm + SM_PH);
    float*    recv  = (float*)(sm + SM_RECV);
    float*    red   = (float*)(sm + SM_RED);
    float*    bc    = (float*)(sm + SM_BCAST);
    float*    srecv = (float*)(sm + SM_SRECV);

    if (tid == 0) {
        mbar_init(mbarP, 256);
        mbar_init(mbarS, 1);
        bc[0] = 0.f; srecv[0] = 0.f;
    }
    if (tid < 256) recv[tid] = 0.f;

    // load my fp8 P slice (rows [rank*256, rank*256+256)) into smem
    {
        const uint4* Pg = (const uint4*)(g_P8 + (size_t)rank * HALFH * HH);
        uint4* Ps = (uint4*)(sm + SM_P);
        for (int idx = tid; idx < HALFH * HH / 16; idx += 512) Ps[idx] = Pg[idx];
    }
    const float corrk = g_corr[tid];   // row-sum correction for row j = tid
    __syncthreads();
    CLUSTER_SYNC_();   // peer mbarriers initialized before any remote arrive

    const int len = g_is64 ? (int)((const long long*)lengths_raw)[b]
                           : ((const int*)lengths_raw)[b];
    const float* Eb  = g_E + (size_t)b * TT * HH;
    const float* smx = g_smax + (size_t)b * TT;

    unsigned pp = 0, ps = 0;
    float c = 0.f;

    // ---- t = 0: p from E[0] ----
    {
        float w = own ? Eb[tid] : 0.f;
        float s1 = warp_sum(w);
        if (lane == 0) red[wid] = s1;
        __syncthreads();
        if (tid == 0) {
            float Sr = 0.f;
            #pragma unroll
            for (int r = 0; r < 16; ++r) Sr += red[r];
            bc[0] = Sr;
            st_remote_f32(sbase + SM_SRECV, peer, Sr);
            mbar_arrive_remote(mbarS, peer);
        }
        __syncthreads();
        mbar_wait(mbarS, ps); ps ^= 1;
        float S = bc[0] + srecv[0];
        if (own) {
            float pk = w * __frcp_rn(S) * corrk;
            unsigned hu = (unsigned)__half_as_ushort(__float2half_rn(pk));
            p_h[u] = hu | (hu << 16);
        }
        if (tid == 0) c = smx[0] + __logf(S);
        __syncthreads();
    }

    // matvec mapping: 8 groups of 64 threads; group g -> local j in [g*32, g*32+32),
    // thread i in group owns k in [i*8, i*8+8)
    const int g = tid >> 6, i = tid & 63;
    const uint2* P2   = (const uint2*)(sm + SM_P) + (size_t)(g * 32) * 64 + i;
    float*       prow = part + g * 512 + i * 8;
    const uint4* ph4  = (const uint4*)(sm + SM_PH) + g * 8;

    for (int t = 1; t < len; ++t) {
        float e = 0.f, smt = 0.f;
        if (own) e = __ldg(Eb + (size_t)t * HH + tid);
        if (tid == 0) smt = __ldg(smx + t);

        // preload my group's 32 p values (half2-broadcast) into registers
        unsigned prs[32];
        #pragma unroll
        for (int r = 0; r < 8; ++r) *(uint4*)&prs[4 * r] = ph4[r];

        __half2 a0 = __float2half2_rn(0.f), a1 = a0, a2 = a0, a3 = a0;
        #pragma unroll
        for (int jj = 0; jj < 32; ++jj) {
            uint2 q = P2[(size_t)jj * 64];
            __half2 hp = u32_h2(prs[jj]);
            a0 = __hfma2(hp, u32_h2(cvt_e4m3x2((unsigned short)(q.x & 0xffffu))), a0);
            a1 = __hfma2(hp, u32_h2(cvt_e4m3x2((unsigned short)(q.x >> 16))),     a1);
            a2 = __hfma2(hp, u32_h2(cvt_e4m3x2((unsigned short)(q.y & 0xffffu))), a2);
            a3 = __hfma2(hp, u32_h2(cvt_e4m3x2((unsigned short)(q.y >> 16))),     a3);
        }
        float2 f0 = __half22float2(a0), f1 = __half22float2(a1);
        float2 f2 = __half22float2(a2), f3 = __half22float2(a3);
        *(float4*)prow       = make_float4(f0.x, f0.y, f1.x, f1.y);
        *(float4*)(prow + 4) = make_float4(f2.x, f2.y, f3.x, f3.y);
        __syncthreads();

        // reduce 8 group partials for global k = tid
        float tot = 0.f;
        #pragma unroll
        for (int r = 0; r < 8; ++r) tot += part[r * 512 + tid];

        // ship peer's half of the partial vector to peer's recv[]
        if (!own) {
            st_remote_f32(sbase + SM_RECV + 4u * (unsigned)u, peer, tot);
            mbar_arrive_remote(mbarP, peer);
        }
        mbar_wait(mbarP, pp); pp ^= 1;

        float w = own ? e * (tot + recv[u]) : 0.f;
        float s1 = warp_sum(w);
        if (lane == 0) red[wid] = s1;
        __syncthreads();
        if (tid == 0) {
            float Sr = 0.f;
            #pragma unroll
            for (int r = 0; r < 16; ++r) Sr += red[r];
            bc[0] = Sr;
            st_remote_f32(sbase + SM_SRECV, peer, Sr);
            mbar_arrive_remote(mbarS, peer);
        }
        __syncthreads();
        mbar_wait(mbarS, ps); ps ^= 1;
        float S = bc[0] + srecv[0];
        if (own) {
            float pk = w * __frcp_rn(S) * corrk;
            unsigned hu = (unsigned)__half_as_ushort(__float2half_rn(pk));
            p_h[u] = hu | (hu << 16);
        }
        if (tid == 0) c += smt + __logf(S) - LOG256;
        __syncthreads();
    }

    if (tid == 0 && rank == 0) out[b] = c;
    CLUSTER_SYNC_();
}

// ---------------- launcher ----------------
extern "C" void kernel_launch(void* const* d_in, const int* in_sizes, int n_in,
                              void* d_out, int out_size) {
    const void*  obs     = d_in[0];
    const void*  lengths = d_in[1];
    const float* emis    = (const float*)d_in[2];
    const float* tran    = (const float*)d_in[3];
    const float* priors  = (const float*)d_in[4];
    float* out = (float*)d_out;

    cudaFuncSetAttribute(forward_kernel, cudaFuncAttributeMaxDynamicSharedMemorySize, SMEM_TOTAL);

    detect_kernel<<<1, 32>>>((const int*)obs);
    lse_kernel<<<SS * HH, 256>>>(emis);
    transpose_kernel<<<dim3((VV + 31) / 32, HH / 32, SS), dim3(32, 8)>>>(emis);
    psoftmax_kernel<<<HH, 256>>>(tran);
    emE_kernel<<<dim3(TT, BB), 128>>>(obs, priors);
    forward_kernel<<<BB * 2, 512, SMEM_TOTAL>>>(lengths, out);
}